// round 14
// baseline (speedup 1.0000x reference)
#include <cuda_runtime.h>
#include <cuda_fp16.h>
#include <cstdint>
#include <cstddef>

#define NBOX 1024
#define S    32
#define C    64
#define HF   192
#define WF   192

// ---------------- device scratch (no allocation allowed) ----------------
__device__ __half g_h0[NBOX * S * S * C];   // conv2 out
__device__ __half g_h1[NBOX * S * S * C];   // conv1 out / conv2 in
// fragment-ordered half weights: [conv][tap][ks][block][lane] -> uint2 (4 halves)
__device__ __half g_wfrag[2 * 9 * 4 * 8 * 32 * 4];
// outconv B fragments: [cls][tap][ks][lane] -> uint2 (4 halves), col 0 = class weights
__device__ __half g_ofrag[3 * 9 * 4 * 32 * 4];

// ---------------- helpers ----------------
__device__ __forceinline__ uint32_t smem_u32(const void* p) {
    uint32_t a;
    asm("{ .reg .u64 t; cvta.to.shared.u64 t, %1; cvt.u32.u64 %0, t; }" : "=r"(a) : "l"(p));
    return a;
}
__device__ __forceinline__ void ldmatrix_x4(uint32_t* r, uint32_t addr) {
    asm volatile("ldmatrix.sync.aligned.m8n8.x4.shared.b16 {%0,%1,%2,%3}, [%4];"
                 : "=r"(r[0]), "=r"(r[1]), "=r"(r[2]), "=r"(r[3]) : "r"(addr));
}
__device__ __forceinline__ void mma16816(float* d, const uint32_t* a, uint32_t b0, uint32_t b1) {
    asm volatile(
        "mma.sync.aligned.m16n8k16.row.col.f32.f16.f16.f32 "
        "{%0,%1,%2,%3}, {%4,%5,%6,%7}, {%8,%9}, {%0,%1,%2,%3};"
        : "+f"(d[0]), "+f"(d[1]), "+f"(d[2]), "+f"(d[3])
        : "r"(a[0]), "r"(a[1]), "r"(a[2]), "r"(a[3]), "r"(b0), "r"(b1));
}

// ---------------- Kernel 0a: conv weight prep -> B fragment layout (oc-permuted) -------
__global__ void __launch_bounds__(256) wprep_kernel(const float* __restrict__ c1w,
                                                    const float* __restrict__ c2w) {
    int b = blockIdx.x;            // 0..17 = conv*9 + tap
    int cw = b / 9, kk = b % 9;
    const float* src = (cw ? c2w : c1w) + kk * 4096;   // [ic][oc] slice
    __half* dst = g_wfrag + b * 4096;
#pragma unroll
    for (int i = 0; i < 16; i++) {
        int e = i * 256 + threadIdx.x;   // e = ic*64 + oc
        int ic = e >> 6, oc = e & 63;
        int ks = ic >> 4, k = ic & 15;
        int g  = oc >> 5, o = oc & 31;
        int cc = o >> 3, ni = (o >> 1) & 3, b2 = o & 1;
        int block = g * 4 + ni;
        int v = cc * 2 + b2;
        int rec = (ks * 8 + block) * 32 + v * 4 + ((k & 7) >> 1);
        int h = (k & 1) + ((k & 8) >> 2);
        dst[rec * 4 + h] = __float2half_rn(src[e]);
    }
}

// ---------------- Kernel 0b: outconv weight prep -> per-class B fragments -------------
// ow layout [ky][kx][ic][3]. For class cl, tap kk: B[k][0] = w(ic = ks*16+k), cols 1..7 = 0.
__global__ void __launch_bounds__(256) owprep_kernel(const float* __restrict__ ow) {
    int b = blockIdx.x;            // 0..26 = cl*9 + tap
    int cl = b / 9, kk = b % 9;
    __half* dst = g_ofrag + b * 512;   // 4 ks * 32 lanes * 4 halves
    int tid = threadIdx.x;
    // zero the region (512 halves = 128 uint2)
    if (tid < 128) ((uint2*)dst)[tid] = make_uint2(0u, 0u);
    __syncthreads();
    if (tid < 64) {
        int ic = tid;
        int ks = ic >> 4, k = ic & 15;
        int lane = (k & 7) >> 1;           // col 0 -> lanes 0..3
        int h = (k & 1) + ((k & 8) >> 2);
        float v = ow[(kk * 64 + ic) * 3 + cl];
        dst[(ks * 32 + lane) * 4 + h] = __float2half_rn(v);
    }
}

// ---------------- shared conv mainloop + epilogue ----------------
struct ConvCore {
    template <typename StageFn>
    __device__ __forceinline__ static void run(char* sm, uint32_t smb,
                                               __half* __restrict__ outh,
                                               const __half* __restrict__ wfrag,
                                               const float* __restrict__ bias,
                                               int box, int y0, int tid,
                                               StageFn stage) {
        stage();   // fill halo tile [10][34][64] half, chunk-swizzled
        __syncthreads();

        int lane = tid & 31, w = tid >> 5;
        int mt0   = (w & 3) * 64;
        int n0    = (w >> 2) * 32;
        int nbase = (w >> 2) * 4;
        int lr    = lane & 15;
        int khalf = lane >> 4;

        uint32_t pixbase[4];
#pragma unroll
        for (int mi = 0; mi < 4; mi++) {
            int m = mt0 + mi * 16 + lr;
            pixbase[mi] = (uint32_t)((m >> 5) * 34 + (m & 31));
        }

        const uint2* wf = (const uint2*)wfrag;

        float acc[4][4][4];
#pragma unroll
        for (int mi = 0; mi < 4; mi++)
#pragma unroll
            for (int ni = 0; ni < 4; ni++)
#pragma unroll
                for (int k = 0; k < 4; k++) acc[mi][ni][k] = 0.0f;

#pragma unroll
        for (int tap = 0; tap < 9; tap++) {
            int ky = tap / 3, kx = tap - ky * 3;
            uint32_t shift = (uint32_t)(ky * 34 + kx);
            const uint2* wt = wf + tap * 1024;
#pragma unroll
            for (int ks = 0; ks < 4; ks++) {
                uint2 b[4];
#pragma unroll
                for (int ni = 0; ni < 4; ni++)
                    b[ni] = __ldg(wt + (ks * 8 + nbase + ni) * 32 + lane);
                uint32_t kc = (uint32_t)(ks * 2 + khalf);
                uint32_t a[4][4];
#pragma unroll
                for (int mi = 0; mi < 4; mi++) {
                    uint32_t pix = pixbase[mi] + shift;
                    uint32_t ad = smb + pix * 128 + (((kc ^ (pix & 7)) & 7) << 4);
                    ldmatrix_x4(a[mi], ad);
                }
#pragma unroll
                for (int ni = 0; ni < 4; ni++)
#pragma unroll
                    for (int mi = 0; mi < 4; mi++)
                        mma16816(acc[mi][ni], a[mi], b[ni].x, b[ni].y);
            }
        }

        // epilogue: bias + relu -> coalesced STG.128 (oc-permuted fragment layout)
        int rowg = lane >> 2;
        int cq   = lane & 3;
        int ocb  = n0 + cq * 8;
        float4 bA = __ldg((const float4*)(bias + ocb));
        float4 bB = __ldg((const float4*)(bias + ocb + 4));
        float bb[8] = {bA.x, bA.y, bA.z, bA.w, bB.x, bB.y, bB.z, bB.w};
        size_t obase = (size_t)box * 65536 + (size_t)y0 * 32 * 64;
#pragma unroll
        for (int mi = 0; mi < 4; mi++) {
#pragma unroll
            for (int h = 0; h < 2; h++) {
                int m = mt0 + mi * 16 + rowg + h * 8;
                __half2 u[4];
#pragma unroll
                for (int ni = 0; ni < 4; ni++) {
                    float v0 = fmaxf(acc[mi][ni][h * 2 + 0] + bb[ni * 2 + 0], 0.0f);
                    float v1 = fmaxf(acc[mi][ni][h * 2 + 1] + bb[ni * 2 + 1], 0.0f);
                    u[ni] = __floats2half2_rn(v0, v1);
                }
                *(uint4*)(outh + obase + (size_t)m * 64 + ocb) = *(uint4*)u;
            }
        }
    }
};

// ---------------- Kernel 1: conv1 with FUSED crop_and_resize staging ----------------
__global__ void __launch_bounds__(256, 2) conv1_fused_kernel(const float* __restrict__ feat,
                                                             const float* __restrict__ boxes,
                                                             const int* __restrict__ box_ids,
                                                             __half* __restrict__ outh,
                                                             const __half* __restrict__ wfrag,
                                                             const float* __restrict__ bias) {
    __shared__ char sm[10 * 34 * 128];
    uint32_t smb = smem_u32(sm);
    int tid = threadIdx.x;
    int box = blockIdx.y;
    int y0  = blockIdx.x * 8;

    float by1 = boxes[box * 4 + 0];
    float bx1 = boxes[box * 4 + 1];
    float by2 = boxes[box * 4 + 2];
    float bx2 = boxes[box * 4 + 3];
    const float* fb = feat + (size_t)box_ids[box] * HF * WF * C;

    ConvCore::run(sm, smb, outh, wfrag, bias, box, y0, tid, [&]() {
#pragma unroll
        for (int i = 0; i < 11; i++) {
            int q = i * 256 + tid;           // 16B chunk id, 0..2719
            if (q < 2720) {
                int p = q >> 3, c = q & 7;   // halo pixel, channel chunk (8 ch)
                int r = p / 34, xi = p - r * 34;
                int gy = y0 - 1 + r, gx = xi - 1;
                uint4 v = make_uint4(0u, 0u, 0u, 0u);
                if ((unsigned)gy < 32u && (unsigned)gx < 32u) {
                    float ty = (float)gy * (1.0f / 31.0f);
                    float ys = (by1 + ty * (by2 - by1)) * 191.0f;
                    float y0f = fminf(fmaxf(floorf(ys), 0.0f), 191.0f);
                    float wy = ys - y0f;
                    int y0i = (int)y0f;
                    int y1i = min(y0i + 1, 191);

                    float tx = (float)gx * (1.0f / 31.0f);
                    float xs = (bx1 + tx * (bx2 - bx1)) * 191.0f;
                    float x0f = fminf(fmaxf(floorf(xs), 0.0f), 191.0f);
                    float wx = xs - x0f;
                    int x0i = (int)x0f;
                    int x1i = min(x0i + 1, 191);

                    int c0 = c * 8;
                    const float4* p00 = (const float4*)(fb + ((size_t)y0i * WF + x0i) * C + c0);
                    const float4* p01 = (const float4*)(fb + ((size_t)y0i * WF + x1i) * C + c0);
                    const float4* p10 = (const float4*)(fb + ((size_t)y1i * WF + x0i) * C + c0);
                    const float4* p11 = (const float4*)(fb + ((size_t)y1i * WF + x1i) * C + c0);
                    float omwx = 1.0f - wx, omwy = 1.0f - wy;
                    __half2 hh[4];
#pragma unroll
                    for (int h = 0; h < 2; h++) {
                        float4 v00 = p00[h], v01 = p01[h], v10 = p10[h], v11 = p11[h];
                        float4 rr;
                        rr.x = (v00.x * omwx + v01.x * wx) * omwy + (v10.x * omwx + v11.x * wx) * wy;
                        rr.y = (v00.y * omwx + v01.y * wx) * omwy + (v10.y * omwx + v11.y * wx) * wy;
                        rr.z = (v00.z * omwx + v01.z * wx) * omwy + (v10.z * omwx + v11.z * wx) * wy;
                        rr.w = (v00.w * omwx + v01.w * wx) * omwy + (v10.w * omwx + v11.w * wx) * wy;
                        hh[h * 2 + 0] = __floats2half2_rn(rr.x, rr.y);
                        hh[h * 2 + 1] = __floats2half2_rn(rr.z, rr.w);
                    }
                    v = *(uint4*)hh;
                }
                *(uint4*)(sm + p * 128 + ((c ^ (p & 7)) << 4)) = v;
            }
        }
    });
}

// ---------------- Kernel 2: conv2 (halo from g_h1, proven staging) ----------------
__global__ void __launch_bounds__(256, 2) conv_mma_kernel(const __half* __restrict__ in,
                                                          __half* __restrict__ outh,
                                                          const __half* __restrict__ wfrag,
                                                          const float* __restrict__ bias) {
    __shared__ char sm[10 * 34 * 128];
    uint32_t smb = smem_u32(sm);
    int tid = threadIdx.x;
    int box = blockIdx.y;
    int y0  = blockIdx.x * 8;
    const char* inb = (const char*)(in + (size_t)box * 65536);

    ConvCore::run(sm, smb, outh, wfrag, bias, box, y0, tid, [&]() {
#pragma unroll
        for (int i = 0; i < 11; i++) {
            int q = i * 256 + tid;           // 16B chunk id, 0..2719
            if (q < 2720) {
                int p = q >> 3, c = q & 7;
                int r = p / 34, xs = p - r * 34;
                int gy = y0 - 1 + r, gx = xs - 1;
                uint4 v = make_uint4(0u, 0u, 0u, 0u);
                if ((unsigned)gy < 32u && (unsigned)gx < 32u)
                    v = *(const uint4*)(inb + ((size_t)(gy * 32 + gx)) * 128 + c * 16);
                *(uint4*)(sm + p * 128 + ((c ^ (p & 7)) << 4)) = v;
            }
        }
    });
}

// ---------------- Kernel 3: 3x3 VALID conv 64->1 via mma (selected class) -------------
// grid (4, NBOX), 256 threads = 8 warps, warp w: M-tile = w*32 (32 px of the 8x32 tile).
// Stage rows y0..y0+9, x 0..31 (x 32,33 zero-pad) — same swizzled layout as conv.
__global__ void __launch_bounds__(256, 2) outconv_mma_kernel(const int* __restrict__ cls,
                                                             const float* __restrict__ obias,
                                                             float* __restrict__ out) {
    __shared__ char sm[10 * 34 * 128];
    uint32_t smb = smem_u32(sm);
    int tid = threadIdx.x;
    int box = blockIdx.y;
    int y0  = blockIdx.x * 8;
    int cl  = __ldg(cls + box);
    const char* inb = (const char*)(g_h0 + (size_t)box * 65536);

    // stage tile: rows y0..y0+9 (no negative halo; VALID conv)
#pragma unroll
    for (int i = 0; i < 11; i++) {
        int q = i * 256 + tid;
        if (q < 2720) {
            int p = q >> 3, c = q & 7;
            int r = p / 34, xi = p - r * 34;
            int gy = y0 + r, gx = xi;
            uint4 v = make_uint4(0u, 0u, 0u, 0u);
            if (gy < 32 && gx < 32)
                v = *(const uint4*)(inb + ((size_t)(gy * 32 + gx)) * 128 + c * 16);
            *(uint4*)(sm + p * 128 + ((c ^ (p & 7)) << 4)) = v;
        }
    }
    __syncthreads();

    int lane = tid & 31, w = tid >> 5;
    int mt0   = w * 32;
    int lr    = lane & 15;
    int khalf = lane >> 4;

    uint32_t pixbase[2];
#pragma unroll
    for (int mi = 0; mi < 2; mi++) {
        int m = mt0 + mi * 16 + lr;
        pixbase[mi] = (uint32_t)((m >> 5) * 34 + (m & 31));
    }

    const uint2* ofr = (const uint2*)(g_ofrag) + (size_t)cl * 9 * 4 * 32;

    float acc[2][4];
#pragma unroll
    for (int mi = 0; mi < 2; mi++)
#pragma unroll
        for (int k = 0; k < 4; k++) acc[mi][k] = 0.0f;

#pragma unroll
    for (int tap = 0; tap < 9; tap++) {
        int ky = tap / 3, kx = tap - ky * 3;
        uint32_t shift = (uint32_t)(ky * 34 + kx);
#pragma unroll
        for (int ks = 0; ks < 4; ks++) {
            uint2 b = __ldg(ofr + (tap * 4 + ks) * 32 + lane);
            uint32_t kc = (uint32_t)(ks * 2 + khalf);
            uint32_t a[2][4];
#pragma unroll
            for (int mi = 0; mi < 2; mi++) {
                uint32_t pix = pixbase[mi] + shift;
                uint32_t ad = smb + pix * 128 + (((kc ^ (pix & 7)) & 7) << 4);
                ldmatrix_x4(a[mi], ad);
            }
#pragma unroll
            for (int mi = 0; mi < 2; mi++)
                mma16816(acc[mi], a[mi], b.x, b.y);
        }
    }

    // epilogue: fragment col 0 lives in lanes with (lane&3)==0; d0=row rowg, d2=row rowg+8
    if ((lane & 3) == 0) {
        float bb = __ldg(obias + cl);
        int rowg = lane >> 2;
#pragma unroll
        for (int mi = 0; mi < 2; mi++) {
#pragma unroll
            for (int h = 0; h < 2; h++) {
                int m = mt0 + mi * 16 + rowg + h * 8;
                int row = m >> 5, x = m & 31;
                int oy = y0 + row;
                if (x < 30 && oy < 30)
                    out[(size_t)box * 900 + oy * 30 + x] = acc[mi][h * 2] + bb;
            }
        }
    }
}

// ---------------- launch ----------------
extern "C" void kernel_launch(void* const* d_in, const int* in_sizes, int n_in,
                              void* d_out, int out_size) {
    const float* features = (const float*)d_in[0];
    const float* boxes    = (const float*)d_in[1];
    const int*   box_ids  = (const int*)d_in[2];
    const int*   cls      = (const int*)d_in[3];
    const float* c1w      = (const float*)d_in[4];
    const float* c1b      = (const float*)d_in[5];
    const float* c2w      = (const float*)d_in[6];
    const float* c2b      = (const float*)d_in[7];
    const float* ow       = (const float*)d_in[8];
    const float* obias    = (const float*)d_in[9];
    float* out = (float*)d_out;

    __half* wf; cudaGetSymbolAddress((void**)&wf, g_wfrag);
    __half* h0; cudaGetSymbolAddress((void**)&h0, g_h0);
    __half* h1; cudaGetSymbolAddress((void**)&h1, g_h1);

    wprep_kernel<<<18, 256>>>(c1w, c2w);
    owprep_kernel<<<27, 256>>>(ow);
    conv1_fused_kernel<<<dim3(4, NBOX), 256>>>(features, boxes, box_ids, h1, wf, c1b);
    conv_mma_kernel<<<dim3(4, NBOX), 256>>>(h1, h0, wf + 9 * 4096, c2b);  // conv2: h1 -> h0
    outconv_mma_kernel<<<dim3(4, NBOX), 256>>>(cls, obias, out);
}

// round 15
// speedup vs baseline: 1.0252x; 1.0252x over previous
#include <cuda_runtime.h>
#include <cuda_fp16.h>
#include <cstdint>
#include <cstddef>

#define NBOX 1024
#define S    32
#define C    64
#define HF   192
#define WF   192

// ---------------- device scratch (no allocation allowed) ----------------
__device__ __half g_h0[NBOX * S * S * C];   // conv2 out
__device__ __half g_h1[NBOX * S * S * C];   // conv1 out / conv2 in
// fragment-ordered half weights: [conv][tap][ks][block][lane] -> uint2 (4 halves)
__device__ __half g_wfrag[2 * 9 * 4 * 8 * 32 * 4];

// ---------------- helpers ----------------
__device__ __forceinline__ uint32_t smem_u32(const void* p) {
    uint32_t a;
    asm("{ .reg .u64 t; cvta.to.shared.u64 t, %1; cvt.u32.u64 %0, t; }" : "=r"(a) : "l"(p));
    return a;
}
__device__ __forceinline__ void ldmatrix_x4(uint32_t* r, uint32_t addr) {
    asm volatile("ldmatrix.sync.aligned.m8n8.x4.shared.b16 {%0,%1,%2,%3}, [%4];"
                 : "=r"(r[0]), "=r"(r[1]), "=r"(r[2]), "=r"(r[3]) : "r"(addr));
}
__device__ __forceinline__ void mma16816(float* d, const uint32_t* a, uint32_t b0, uint32_t b1) {
    asm volatile(
        "mma.sync.aligned.m16n8k16.row.col.f32.f16.f16.f32 "
        "{%0,%1,%2,%3}, {%4,%5,%6,%7}, {%8,%9}, {%0,%1,%2,%3};"
        : "+f"(d[0]), "+f"(d[1]), "+f"(d[2]), "+f"(d[3])
        : "r"(a[0]), "r"(a[1]), "r"(a[2]), "r"(a[3]), "r"(b0), "r"(b1));
}

// ---------------- Kernel 0: conv weight prep -> B fragment layout (oc-permuted) -------
__global__ void __launch_bounds__(256) wprep_kernel(const float* __restrict__ c1w,
                                                    const float* __restrict__ c2w) {
    int b = blockIdx.x;            // 0..17 = conv*9 + tap
    int cw = b / 9, kk = b % 9;
    const float* src = (cw ? c2w : c1w) + kk * 4096;   // [ic][oc] slice
    __half* dst = g_wfrag + b * 4096;
#pragma unroll
    for (int i = 0; i < 16; i++) {
        int e = i * 256 + threadIdx.x;   // e = ic*64 + oc
        int ic = e >> 6, oc = e & 63;
        int ks = ic >> 4, k = ic & 15;
        int g  = oc >> 5, o = oc & 31;
        int cc = o >> 3, ni = (o >> 1) & 3, b2 = o & 1;
        int block = g * 4 + ni;
        int v = cc * 2 + b2;
        int rec = (ks * 8 + block) * 32 + v * 4 + ((k & 7) >> 1);
        int h = (k & 1) + ((k & 8) >> 2);
        dst[rec * 4 + h] = __float2half_rn(src[e]);
    }
}

// ---------------- shared conv mainloop + epilogue (XOR-folded addressing) ----------------
struct ConvCore {
    template <typename StageFn>
    __device__ __forceinline__ static void run(char* sm, uint32_t smb,
                                               __half* __restrict__ outh,
                                               const __half* __restrict__ wfrag,
                                               const float* __restrict__ bias,
                                               int box, int y0, int tid,
                                               StageFn stage) {
        stage();   // fill halo tile [10][34][64] half, chunk-swizzled
        __syncthreads();

        int lane = tid & 31, w = tid >> 5;
        int mt0   = (w & 3) * 64;
        int n0    = (w >> 2) * 32;
        int nbase = (w >> 2) * 4;
        int lr    = lane & 15;
        uint32_t khalf16 = (uint32_t)((lane >> 4) << 4);

        uint32_t pixbase[4];
#pragma unroll
        for (int mi = 0; mi < 4; mi++) {
            int m = mt0 + mi * 16 + lr;
            pixbase[mi] = (uint32_t)((m >> 5) * 34 + (m & 31));
        }

        const uint2* wf = (const uint2*)wfrag;

        float acc[4][4][4];
#pragma unroll
        for (int mi = 0; mi < 4; mi++)
#pragma unroll
            for (int ni = 0; ni < 4; ni++)
#pragma unroll
                for (int k = 0; k < 4; k++) acc[mi][ni][k] = 0.0f;

#pragma unroll
        for (int tap = 0; tap < 9; tap++) {
            int ky = tap / 3, kx = tap - ky * 3;
            uint32_t shift = (uint32_t)(ky * 34 + kx);
            const uint2* wt = wf + tap * 1024;
            // per-tap ldmatrix base addresses: swizzle bits 4..6 = pix&7 (smb 128-aligned)
            uint32_t base[4];
#pragma unroll
            for (int mi = 0; mi < 4; mi++) {
                uint32_t pix = pixbase[mi] + shift;
                base[mi] = (smb + pix * 128 + ((pix & 7) << 4)) ^ khalf16;
            }
#pragma unroll
            for (int ks = 0; ks < 4; ks++) {
                uint2 b[4];
#pragma unroll
                for (int ni = 0; ni < 4; ni++)
                    b[ni] = __ldg(wt + (ks * 8 + nbase + ni) * 32 + lane);
                uint32_t a[4][4];
#pragma unroll
                for (int mi = 0; mi < 4; mi++)
                    ldmatrix_x4(a[mi], base[mi] ^ (uint32_t)(ks << 5));
#pragma unroll
                for (int ni = 0; ni < 4; ni++)
#pragma unroll
                    for (int mi = 0; mi < 4; mi++)
                        mma16816(acc[mi][ni], a[mi], b[ni].x, b[ni].y);
            }
        }

        // epilogue: bias + relu -> coalesced STG.128 (oc-permuted fragment layout)
        int rowg = lane >> 2;
        int cq   = lane & 3;
        int ocb  = n0 + cq * 8;
        float4 bA = __ldg((const float4*)(bias + ocb));
        float4 bB = __ldg((const float4*)(bias + ocb + 4));
        float bb[8] = {bA.x, bA.y, bA.z, bA.w, bB.x, bB.y, bB.z, bB.w};
        size_t obase = (size_t)box * 65536 + (size_t)y0 * 32 * 64;
#pragma unroll
        for (int mi = 0; mi < 4; mi++) {
#pragma unroll
            for (int h = 0; h < 2; h++) {
                int m = mt0 + mi * 16 + rowg + h * 8;
                __half2 u[4];
#pragma unroll
                for (int ni = 0; ni < 4; ni++) {
                    float v0 = fmaxf(acc[mi][ni][h * 2 + 0] + bb[ni * 2 + 0], 0.0f);
                    float v1 = fmaxf(acc[mi][ni][h * 2 + 1] + bb[ni * 2 + 1], 0.0f);
                    u[ni] = __floats2half2_rn(v0, v1);
                }
                *(uint4*)(outh + obase + (size_t)m * 64 + ocb) = *(uint4*)u;
            }
        }
    }
};

// ---------------- Kernel 1: conv1 with FUSED crop_and_resize staging ----------------
__global__ void __launch_bounds__(256, 2) conv1_fused_kernel(const float* __restrict__ feat,
                                                             const float* __restrict__ boxes,
                                                             const int* __restrict__ box_ids,
                                                             __half* __restrict__ outh,
                                                             const __half* __restrict__ wfrag,
                                                             const float* __restrict__ bias) {
    __shared__ __align__(128) char sm[10 * 34 * 128];
    uint32_t smb = smem_u32(sm);
    int tid = threadIdx.x;
    int box = blockIdx.y;
    int y0  = blockIdx.x * 8;

    float by1 = boxes[box * 4 + 0];
    float bx1 = boxes[box * 4 + 1];
    float by2 = boxes[box * 4 + 2];
    float bx2 = boxes[box * 4 + 3];
    const float* fb = feat + (size_t)box_ids[box] * HF * WF * C;

    ConvCore::run(sm, smb, outh, wfrag, bias, box, y0, tid, [&]() {
#pragma unroll
        for (int i = 0; i < 11; i++) {
            int q = i * 256 + tid;           // 16B chunk id, 0..2719
            if (q < 2720) {
                int p = q >> 3, c = q & 7;   // halo pixel, channel chunk (8 ch)
                int r = p / 34, xi = p - r * 34;
                int gy = y0 - 1 + r, gx = xi - 1;
                uint4 v = make_uint4(0u, 0u, 0u, 0u);
                if ((unsigned)gy < 32u && (unsigned)gx < 32u) {
                    float ty = (float)gy * (1.0f / 31.0f);
                    float ys = (by1 + ty * (by2 - by1)) * 191.0f;
                    float y0f = fminf(fmaxf(floorf(ys), 0.0f), 191.0f);
                    float wy = ys - y0f;
                    int y0i = (int)y0f;
                    int y1i = min(y0i + 1, 191);

                    float tx = (float)gx * (1.0f / 31.0f);
                    float xs = (bx1 + tx * (bx2 - bx1)) * 191.0f;
                    float x0f = fminf(fmaxf(floorf(xs), 0.0f), 191.0f);
                    float wx = xs - x0f;
                    int x0i = (int)x0f;
                    int x1i = min(x0i + 1, 191);

                    int c0 = c * 8;
                    const float4* p00 = (const float4*)(fb + ((size_t)y0i * WF + x0i) * C + c0);
                    const float4* p01 = (const float4*)(fb + ((size_t)y0i * WF + x1i) * C + c0);
                    const float4* p10 = (const float4*)(fb + ((size_t)y1i * WF + x0i) * C + c0);
                    const float4* p11 = (const float4*)(fb + ((size_t)y1i * WF + x1i) * C + c0);
                    float omwx = 1.0f - wx, omwy = 1.0f - wy;
                    __half2 hh[4];
#pragma unroll
                    for (int h = 0; h < 2; h++) {
                        float4 v00 = p00[h], v01 = p01[h], v10 = p10[h], v11 = p11[h];
                        float4 rr;
                        rr.x = (v00.x * omwx + v01.x * wx) * omwy + (v10.x * omwx + v11.x * wx) * wy;
                        rr.y = (v00.y * omwx + v01.y * wx) * omwy + (v10.y * omwx + v11.y * wx) * wy;
                        rr.z = (v00.z * omwx + v01.z * wx) * omwy + (v10.z * omwx + v11.z * wx) * wy;
                        rr.w = (v00.w * omwx + v01.w * wx) * omwy + (v10.w * omwx + v11.w * wx) * wy;
                        hh[h * 2 + 0] = __floats2half2_rn(rr.x, rr.y);
                        hh[h * 2 + 1] = __floats2half2_rn(rr.z, rr.w);
                    }
                    v = *(uint4*)hh;
                }
                *(uint4*)(sm + p * 128 + ((c ^ (p & 7)) << 4)) = v;
            }
        }
    });
}

// ---------------- Kernel 2: conv2 (halo from g_h1, proven staging) ----------------
__global__ void __launch_bounds__(256, 2) conv_mma_kernel(const __half* __restrict__ in,
                                                          __half* __restrict__ outh,
                                                          const __half* __restrict__ wfrag,
                                                          const float* __restrict__ bias) {
    __shared__ __align__(128) char sm[10 * 34 * 128];
    uint32_t smb = smem_u32(sm);
    int tid = threadIdx.x;
    int box = blockIdx.y;
    int y0  = blockIdx.x * 8;
    const char* inb = (const char*)(in + (size_t)box * 65536);

    ConvCore::run(sm, smb, outh, wfrag, bias, box, y0, tid, [&]() {
#pragma unroll
        for (int i = 0; i < 11; i++) {
            int q = i * 256 + tid;           // 16B chunk id, 0..2719
            if (q < 2720) {
                int p = q >> 3, c = q & 7;
                int r = p / 34, xs = p - r * 34;
                int gy = y0 - 1 + r, gx = xs - 1;
                uint4 v = make_uint4(0u, 0u, 0u, 0u);
                if ((unsigned)gy < 32u && (unsigned)gx < 32u)
                    v = *(const uint4*)(inb + ((size_t)(gy * 32 + gx)) * 128 + c * 16);
                *(uint4*)(sm + p * 128 + ((c ^ (p & 7)) << 4)) = v;
            }
        }
    });
}

// ---------------- Kernel 3: 3x3 VALID conv 64->1, 4 output cols per team (proven) -----
__global__ void __launch_bounds__(256) outconv_kernel(const float* __restrict__ ow,
                                                      const float* __restrict__ obias,
                                                      const int* __restrict__ cls,
                                                      float* __restrict__ out) {
    __shared__ float sW[576];
    int box = blockIdx.x;
    int cl  = cls[box];
    int tid = threadIdx.x;
    for (int e = tid; e < 576; e += 256) sW[e] = ow[e * 3 + cl];
    __syncthreads();

    int sub = tid & 7, team = tid >> 3;
    int c0 = sub * 8;
    float4 wv[18];
#pragma unroll
    for (int p9 = 0; p9 < 9; p9++) {
        wv[p9 * 2 + 0] = *(const float4*)(sW + p9 * 64 + c0);
        wv[p9 * 2 + 1] = *(const float4*)(sW + p9 * 64 + c0 + 4);
    }
    float bb = obias[cl];
    const __half* inb = g_h0 + (size_t)box * 65536;

    for (int t = team; t < 240; t += 32) {
        int oy  = t >> 3;
        int ox0 = (t & 7) * 4;
        float acc0 = 0.f, acc1 = 0.f, acc2 = 0.f, acc3 = 0.f;
#pragma unroll
        for (int ky = 0; ky < 3; ky++) {
            float colf[6][8];
#pragma unroll
            for (int cc = 0; cc < 6; cc++) {
                int gx = ox0 + cc;
                uint4 raw = make_uint4(0u, 0u, 0u, 0u);
                if (gx < 32)
                    raw = *(const uint4*)(inb + ((size_t)((oy + ky) * 32 + gx)) * 64 + c0);
                const __half2* hp = (const __half2*)&raw;
#pragma unroll
                for (int q = 0; q < 4; q++) {
                    float2 f = __half22float2(hp[q]);
                    colf[cc][q * 2 + 0] = f.x;
                    colf[cc][q * 2 + 1] = f.y;
                }
            }
#pragma unroll
            for (int kx = 0; kx < 3; kx++) {
                const float* w0 = (const float*)&wv[(ky * 3 + kx) * 2];
                float d0 = 0.f, d1 = 0.f, d2 = 0.f, d3 = 0.f;
#pragma unroll
                for (int q = 0; q < 8; q++) {
                    float wq = w0[q];
                    d0 += colf[kx + 0][q] * wq;
                    d1 += colf[kx + 1][q] * wq;
                    d2 += colf[kx + 2][q] * wq;
                    d3 += colf[kx + 3][q] * wq;
                }
                acc0 += d0; acc1 += d1; acc2 += d2; acc3 += d3;
            }
        }
        acc0 += __shfl_down_sync(0xffffffff, acc0, 4, 8);
        acc1 += __shfl_down_sync(0xffffffff, acc1, 4, 8);
        acc2 += __shfl_down_sync(0xffffffff, acc2, 4, 8);
        acc3 += __shfl_down_sync(0xffffffff, acc3, 4, 8);
        acc0 += __shfl_down_sync(0xffffffff, acc0, 2, 8);
        acc1 += __shfl_down_sync(0xffffffff, acc1, 2, 8);
        acc2 += __shfl_down_sync(0xffffffff, acc2, 2, 8);
        acc3 += __shfl_down_sync(0xffffffff, acc3, 2, 8);
        acc0 += __shfl_down_sync(0xffffffff, acc0, 1, 8);
        acc1 += __shfl_down_sync(0xffffffff, acc1, 1, 8);
        acc2 += __shfl_down_sync(0xffffffff, acc2, 1, 8);
        acc3 += __shfl_down_sync(0xffffffff, acc3, 1, 8);
        if (sub == 0) {
            float* ob = out + (size_t)box * 900 + oy * 30 + ox0;
            ob[0] = acc0 + bb;
            ob[1] = acc1 + bb;
            if (ox0 + 2 < 30) {
                ob[2] = acc2 + bb;
                ob[3] = acc3 + bb;
            }
        }
    }
}

// ---------------- launch ----------------
extern "C" void kernel_launch(void* const* d_in, const int* in_sizes, int n_in,
                              void* d_out, int out_size) {
    const float* features = (const float*)d_in[0];
    const float* boxes    = (const float*)d_in[1];
    const int*   box_ids  = (const int*)d_in[2];
    const int*   cls      = (const int*)d_in[3];
    const float* c1w      = (const float*)d_in[4];
    const float* c1b      = (const float*)d_in[5];
    const float* c2w      = (const float*)d_in[6];
    const float* c2b      = (const float*)d_in[7];
    const float* ow       = (const float*)d_in[8];
    const float* obias    = (const float*)d_in[9];
    float* out = (float*)d_out;

    __half* wf; cudaGetSymbolAddress((void**)&wf, g_wfrag);
    __half* h0; cudaGetSymbolAddress((void**)&h0, g_h0);
    __half* h1; cudaGetSymbolAddress((void**)&h1, g_h1);

    wprep_kernel<<<18, 256>>>(c1w, c2w);
    conv1_fused_kernel<<<dim3(4, NBOX), 256>>>(features, boxes, box_ids, h1, wf, c1b);
    conv_mma_kernel<<<dim3(4, NBOX), 256>>>(h1, h0, wf + 9 * 4096, c2b);  // conv2: h1 -> h0
    outconv_kernel<<<NBOX, 256>>>(ow, obias, cls, out);
}

// round 16
// speedup vs baseline: 1.0262x; 1.0010x over previous
#include <cuda_runtime.h>
#include <cuda_fp16.h>
#include <cstdint>
#include <cstddef>

#define NBOX 1024
#define S    32
#define C    64
#define HF   192
#define WF   192

// ---------------- device scratch (no allocation allowed) ----------------
__device__ __half g_h0[NBOX * S * S * C];   // conv2 out
__device__ __half g_h1[NBOX * S * S * C];   // conv1 out / conv2 in
// fragment-ordered half weights: [conv][tap][ks][block][lane] -> uint2 (4 halves)
__device__ __half g_wfrag[2 * 9 * 4 * 8 * 32 * 4];

// ---------------- helpers ----------------
__device__ __forceinline__ uint32_t smem_u32(const void* p) {
    uint32_t a;
    asm("{ .reg .u64 t; cvta.to.shared.u64 t, %1; cvt.u32.u64 %0, t; }" : "=r"(a) : "l"(p));
    return a;
}
__device__ __forceinline__ void ldmatrix_x4(uint32_t* r, uint32_t addr) {
    asm volatile("ldmatrix.sync.aligned.m8n8.x4.shared.b16 {%0,%1,%2,%3}, [%4];"
                 : "=r"(r[0]), "=r"(r[1]), "=r"(r[2]), "=r"(r[3]) : "r"(addr));
}
__device__ __forceinline__ void mma16816(float* d, const uint32_t* a, uint32_t b0, uint32_t b1) {
    asm volatile(
        "mma.sync.aligned.m16n8k16.row.col.f32.f16.f16.f32 "
        "{%0,%1,%2,%3}, {%4,%5,%6,%7}, {%8,%9}, {%0,%1,%2,%3};"
        : "+f"(d[0]), "+f"(d[1]), "+f"(d[2]), "+f"(d[3])
        : "r"(a[0]), "r"(a[1]), "r"(a[2]), "r"(a[3]), "r"(b0), "r"(b1));
}
__device__ __forceinline__ void cp_async16(uint32_t saddr, const void* gaddr, uint32_t srcsize) {
    asm volatile("cp.async.cg.shared.global [%0], [%1], 16, %2;"
                 :: "r"(saddr), "l"(gaddr), "r"(srcsize) : "memory");
}
__device__ __forceinline__ void cp_async_wait_all() {
    asm volatile("cp.async.commit_group;\ncp.async.wait_group 0;" ::: "memory");
}

// ---------------- Kernel 0: conv weight prep -> B fragment layout (oc-permuted) -------
__global__ void __launch_bounds__(256) wprep_kernel(const float* __restrict__ c1w,
                                                    const float* __restrict__ c2w) {
    int b = blockIdx.x;            // 0..17 = conv*9 + tap
    int cw = b / 9, kk = b % 9;
    const float* src = (cw ? c2w : c1w) + kk * 4096;   // [ic][oc] slice
    __half* dst = g_wfrag + b * 4096;
#pragma unroll
    for (int i = 0; i < 16; i++) {
        int e = i * 256 + threadIdx.x;   // e = ic*64 + oc
        int ic = e >> 6, oc = e & 63;
        int ks = ic >> 4, k = ic & 15;
        int g  = oc >> 5, o = oc & 31;
        int cc = o >> 3, ni = (o >> 1) & 3, b2 = o & 1;
        int block = g * 4 + ni;
        int v = cc * 2 + b2;
        int rec = (ks * 8 + block) * 32 + v * 4 + ((k & 7) >> 1);
        int h = (k & 1) + ((k & 8) >> 2);
        dst[rec * 4 + h] = __float2half_rn(src[e]);
    }
}

// ---------------- shared conv mainloop + epilogue (XOR-folded addressing) ----------------
struct ConvCore {
    template <typename StageFn>
    __device__ __forceinline__ static void run(char* sm, uint32_t smb,
                                               __half* __restrict__ outh,
                                               const __half* __restrict__ wfrag,
                                               const float* __restrict__ bias,
                                               int box, int y0, int tid,
                                               StageFn stage) {
        stage();   // fill halo tile [10][34][64] half, chunk-swizzled
        __syncthreads();

        int lane = tid & 31, w = tid >> 5;
        int mt0   = (w & 3) * 64;
        int n0    = (w >> 2) * 32;
        int nbase = (w >> 2) * 4;
        int lr    = lane & 15;
        uint32_t khalf16 = (uint32_t)((lane >> 4) << 4);

        uint32_t pixbase[4];
#pragma unroll
        for (int mi = 0; mi < 4; mi++) {
            int m = mt0 + mi * 16 + lr;
            pixbase[mi] = (uint32_t)((m >> 5) * 34 + (m & 31));
        }

        const uint2* wf = (const uint2*)wfrag;

        float acc[4][4][4];
#pragma unroll
        for (int mi = 0; mi < 4; mi++)
#pragma unroll
            for (int ni = 0; ni < 4; ni++)
#pragma unroll
                for (int k = 0; k < 4; k++) acc[mi][ni][k] = 0.0f;

#pragma unroll
        for (int tap = 0; tap < 9; tap++) {
            int ky = tap / 3, kx = tap - ky * 3;
            uint32_t shift = (uint32_t)(ky * 34 + kx);
            const uint2* wt = wf + tap * 1024;
            uint32_t base[4];
#pragma unroll
            for (int mi = 0; mi < 4; mi++) {
                uint32_t pix = pixbase[mi] + shift;
                base[mi] = (smb + pix * 128 + ((pix & 7) << 4)) ^ khalf16;
            }
#pragma unroll
            for (int ks = 0; ks < 4; ks++) {
                uint2 b[4];
#pragma unroll
                for (int ni = 0; ni < 4; ni++)
                    b[ni] = __ldg(wt + (ks * 8 + nbase + ni) * 32 + lane);
                uint32_t a[4][4];
#pragma unroll
                for (int mi = 0; mi < 4; mi++)
                    ldmatrix_x4(a[mi], base[mi] ^ (uint32_t)(ks << 5));
#pragma unroll
                for (int ni = 0; ni < 4; ni++)
#pragma unroll
                    for (int mi = 0; mi < 4; mi++)
                        mma16816(acc[mi][ni], a[mi], b[ni].x, b[ni].y);
            }
        }

        // epilogue: bias + relu -> coalesced STG.128 (oc-permuted fragment layout)
        int rowg = lane >> 2;
        int cq   = lane & 3;
        int ocb  = n0 + cq * 8;
        float4 bA = __ldg((const float4*)(bias + ocb));
        float4 bB = __ldg((const float4*)(bias + ocb + 4));
        float bb[8] = {bA.x, bA.y, bA.z, bA.w, bB.x, bB.y, bB.z, bB.w};
        size_t obase = (size_t)box * 65536 + (size_t)y0 * 32 * 64;
#pragma unroll
        for (int mi = 0; mi < 4; mi++) {
#pragma unroll
            for (int h = 0; h < 2; h++) {
                int m = mt0 + mi * 16 + rowg + h * 8;
                __half2 u[4];
#pragma unroll
                for (int ni = 0; ni < 4; ni++) {
                    float v0 = fmaxf(acc[mi][ni][h * 2 + 0] + bb[ni * 2 + 0], 0.0f);
                    float v1 = fmaxf(acc[mi][ni][h * 2 + 1] + bb[ni * 2 + 1], 0.0f);
                    u[ni] = __floats2half2_rn(v0, v1);
                }
                *(uint4*)(outh + obase + (size_t)m * 64 + ocb) = *(uint4*)u;
            }
        }
    }
};

// ---------------- Kernel 1: conv1 with FUSED crop_and_resize staging ----------------
__global__ void __launch_bounds__(256, 2) conv1_fused_kernel(const float* __restrict__ feat,
                                                             const float* __restrict__ boxes,
                                                             const int* __restrict__ box_ids,
                                                             __half* __restrict__ outh,
                                                             const __half* __restrict__ wfrag,
                                                             const float* __restrict__ bias) {
    __shared__ __align__(128) char sm[10 * 34 * 128];
    uint32_t smb = smem_u32(sm);
    int tid = threadIdx.x;
    int box = blockIdx.y;
    int y0  = blockIdx.x * 8;

    float by1 = boxes[box * 4 + 0];
    float bx1 = boxes[box * 4 + 1];
    float by2 = boxes[box * 4 + 2];
    float bx2 = boxes[box * 4 + 3];
    const float* fb = feat + (size_t)box_ids[box] * HF * WF * C;

    ConvCore::run(sm, smb, outh, wfrag, bias, box, y0, tid, [&]() {
#pragma unroll
        for (int i = 0; i < 11; i++) {
            int q = i * 256 + tid;           // 16B chunk id, 0..2719
            if (q < 2720) {
                int p = q >> 3, c = q & 7;   // halo pixel, channel chunk (8 ch)
                int r = p / 34, xi = p - r * 34;
                int gy = y0 - 1 + r, gx = xi - 1;
                uint4 v = make_uint4(0u, 0u, 0u, 0u);
                if ((unsigned)gy < 32u && (unsigned)gx < 32u) {
                    float ty = (float)gy * (1.0f / 31.0f);
                    float ys = (by1 + ty * (by2 - by1)) * 191.0f;
                    float y0f = fminf(fmaxf(floorf(ys), 0.0f), 191.0f);
                    float wy = ys - y0f;
                    int y0i = (int)y0f;
                    int y1i = min(y0i + 1, 191);

                    float tx = (float)gx * (1.0f / 31.0f);
                    float xs = (bx1 + tx * (bx2 - bx1)) * 191.0f;
                    float x0f = fminf(fmaxf(floorf(xs), 0.0f), 191.0f);
                    float wx = xs - x0f;
                    int x0i = (int)x0f;
                    int x1i = min(x0i + 1, 191);

                    int c0 = c * 8;
                    const float4* p00 = (const float4*)(fb + ((size_t)y0i * WF + x0i) * C + c0);
                    const float4* p01 = (const float4*)(fb + ((size_t)y0i * WF + x1i) * C + c0);
                    const float4* p10 = (const float4*)(fb + ((size_t)y1i * WF + x0i) * C + c0);
                    const float4* p11 = (const float4*)(fb + ((size_t)y1i * WF + x1i) * C + c0);
                    float omwx = 1.0f - wx, omwy = 1.0f - wy;
                    __half2 hh[4];
#pragma unroll
                    for (int h = 0; h < 2; h++) {
                        float4 v00 = p00[h], v01 = p01[h], v10 = p10[h], v11 = p11[h];
                        float4 rr;
                        rr.x = (v00.x * omwx + v01.x * wx) * omwy + (v10.x * omwx + v11.x * wx) * wy;
                        rr.y = (v00.y * omwx + v01.y * wx) * omwy + (v10.y * omwx + v11.y * wx) * wy;
                        rr.z = (v00.z * omwx + v01.z * wx) * omwy + (v10.z * omwx + v11.z * wx) * wy;
                        rr.w = (v00.w * omwx + v01.w * wx) * omwy + (v10.w * omwx + v11.w * wx) * wy;
                        hh[h * 2 + 0] = __floats2half2_rn(rr.x, rr.y);
                        hh[h * 2 + 1] = __floats2half2_rn(rr.z, rr.w);
                    }
                    v = *(uint4*)hh;
                }
                *(uint4*)(sm + p * 128 + ((c ^ (p & 7)) << 4)) = v;
            }
        }
    });
}

// ---------------- Kernel 2: conv2 (halo from g_h1, cp.async staging) ----------------
__global__ void __launch_bounds__(256, 2) conv_mma_kernel(const __half* __restrict__ in,
                                                          __half* __restrict__ outh,
                                                          const __half* __restrict__ wfrag,
                                                          const float* __restrict__ bias) {
    __shared__ __align__(128) char sm[10 * 34 * 128];
    uint32_t smb = smem_u32(sm);
    int tid = threadIdx.x;
    int box = blockIdx.y;
    int y0  = blockIdx.x * 8;
    const char* inb = (const char*)(in + (size_t)box * 65536);

    ConvCore::run(sm, smb, outh, wfrag, bias, box, y0, tid, [&]() {
#pragma unroll
        for (int i = 0; i < 11; i++) {
            int q = i * 256 + tid;           // 16B chunk id, 0..2719
            if (q < 2720) {
                int p = q >> 3, c = q & 7;
                int r = p / 34, xs = p - r * 34;
                int gy = y0 - 1 + r, gx = xs - 1;
                bool ok = ((unsigned)gy < 32u && (unsigned)gx < 32u);
                const char* src = ok ? (inb + ((size_t)(gy * 32 + gx)) * 128 + c * 16) : inb;
                cp_async16(smb + p * 128 + ((c ^ (p & 7)) << 4), src, ok ? 16u : 0u);
            }
        }
        cp_async_wait_all();
    });
}

// ---------------- Kernel 3: 3x3 VALID conv 64->1, 16-lane teams x 4 output cols -------
__global__ void __launch_bounds__(256, 3) outconv_kernel(const float* __restrict__ ow,
                                                         const float* __restrict__ obias,
                                                         const int* __restrict__ cls,
                                                         float* __restrict__ out) {
    __shared__ float sW[576];
    int box = blockIdx.x;
    int cl  = cls[box];
    int tid = threadIdx.x;
    for (int e = tid; e < 576; e += 256) sW[e] = ow[e * 3 + cl];
    __syncthreads();

    int sub = tid & 15, team = tid >> 4;   // 16 teams of 16 lanes
    int c0 = sub * 4;                      // 4 channels per lane
    float4 wv[9];
#pragma unroll
    for (int p9 = 0; p9 < 9; p9++)
        wv[p9] = *(const float4*)(sW + p9 * 64 + c0);
    float bb = obias[cl];
    const __half* inb = g_h0 + (size_t)box * 65536;

    // 240 team-iters: 30 rows x 8 column-groups of 4
    for (int t = team; t < 240; t += 16) {
        int oy  = t >> 3;
        int ox0 = (t & 7) * 4;
        float acc0 = 0.f, acc1 = 0.f, acc2 = 0.f, acc3 = 0.f;
#pragma unroll
        for (int ky = 0; ky < 3; ky++) {
            float colf[6][4];
#pragma unroll
            for (int cc = 0; cc < 6; cc++) {
                int gx = ox0 + cc;
                uint2 raw = make_uint2(0u, 0u);
                if (gx < 32)
                    raw = *(const uint2*)(inb + ((size_t)((oy + ky) * 32 + gx)) * 64 + c0);
                const __half2* hp = (const __half2*)&raw;
                float2 f0 = __half22float2(hp[0]);
                float2 f1 = __half22float2(hp[1]);
                colf[cc][0] = f0.x; colf[cc][1] = f0.y;
                colf[cc][2] = f1.x; colf[cc][3] = f1.y;
            }
#pragma unroll
            for (int kx = 0; kx < 3; kx++) {
                const float* w0 = (const float*)&wv[ky * 3 + kx];
                float d0 = 0.f, d1 = 0.f, d2 = 0.f, d3 = 0.f;
#pragma unroll
                for (int q = 0; q < 4; q++) {
                    float wq = w0[q];
                    d0 += colf[kx + 0][q] * wq;
                    d1 += colf[kx + 1][q] * wq;
                    d2 += colf[kx + 2][q] * wq;
                    d3 += colf[kx + 3][q] * wq;
                }
                acc0 += d0; acc1 += d1; acc2 += d2; acc3 += d3;
            }
        }
        // team reduce over 16 lanes
#pragma unroll
        for (int s = 8; s >= 1; s >>= 1) {
            acc0 += __shfl_down_sync(0xffffffff, acc0, s, 16);
            acc1 += __shfl_down_sync(0xffffffff, acc1, s, 16);
            acc2 += __shfl_down_sync(0xffffffff, acc2, s, 16);
            acc3 += __shfl_down_sync(0xffffffff, acc3, s, 16);
        }
        if (sub == 0) {
            float* ob = out + (size_t)box * 900 + oy * 30 + ox0;
            ob[0] = acc0 + bb;
            ob[1] = acc1 + bb;
            if (ox0 + 2 < 30) {
                ob[2] = acc2 + bb;
                ob[3] = acc3 + bb;
            }
        }
    }
}

// ---------------- launch ----------------
extern "C" void kernel_launch(void* const* d_in, const int* in_sizes, int n_in,
                              void* d_out, int out_size) {
    const float* features = (const float*)d_in[0];
    const float* boxes    = (const float*)d_in[1];
    const int*   box_ids  = (const int*)d_in[2];
    const int*   cls      = (const int*)d_in[3];
    const float* c1w      = (const float*)d_in[4];
    const float* c1b      = (const float*)d_in[5];
    const float* c2w      = (const float*)d_in[6];
    const float* c2b      = (const float*)d_in[7];
    const float* ow       = (const float*)d_in[8];
    const float* obias    = (const float*)d_in[9];
    float* out = (float*)d_out;

    __half* wf; cudaGetSymbolAddress((void**)&wf, g_wfrag);
    __half* h0; cudaGetSymbolAddress((void**)&h0, g_h0);
    __half* h1; cudaGetSymbolAddress((void**)&h1, g_h1);

    wprep_kernel<<<18, 256>>>(c1w, c2w);
    conv1_fused_kernel<<<dim3(4, NBOX), 256>>>(features, boxes, box_ids, h1, wf, c1b);
    conv_mma_kernel<<<dim3(4, NBOX), 256>>>(h1, h0, wf + 9 * 4096, c2b);  // conv2: h1 -> h0
    outconv_kernel<<<NBOX, 256>>>(ow, obias, cls, out);
}